// round 16
// baseline (speedup 1.0000x reference)
#include <cuda_runtime.h>
#include <cuda_fp16.h>
#include <math.h>
#include <stdint.h>

#define BATCH 64
#define SEQ   1024
#define D2    1024
#define DCAT  512
#define D3    1536
#define DA    350
#define CATP  384
#define NW1   384
#define RR    30
#define MLPD  2048
#define KMLP  46080
#define ROWS  65536
#define NEGV  (-1e9f)
#define KSPLIT 18
#define KCHUNK 2560
#define NCH6   40

// ---------------- scratch ----------------
__device__ float g_catc[BATCH * CATP];                     // zero-init; cols >=350 stay 0
__device__ float g_s2[BATCH * RR * SEQ];
__device__ float g_part[KSPLIT * MLPD * BATCH];
__device__ __align__(128) __half g_W1H[NW1 * D2];
__device__ __align__(128) __half g_W2H[32 * 384];          // [r pad 32][n pad 384]
__device__ __align__(128) __half g_AH[BATCH * 32 * SEQ];   // probs fp16, rows 30,31 zero
__device__ __align__(128) __half g_BM[BATCH * KMLP];
__device__ __align__(128) __half g_WmH[(size_t)MLPD * KMLP];  // Wm fp16 (stream-converted)

// ---------------- helpers ----------------
__device__ __forceinline__ uint32_t smem_u32(const void* p) {
    uint32_t r;
    asm("{ .reg .u64 t; cvta.to.shared.u64 t, %1; cvt.u32.u64 %0, t; }" : "=r"(r) : "l"(p));
    return r;
}
__device__ __forceinline__ void ldsm4(uint32_t* r, uint32_t addr) {
    asm volatile("ldmatrix.sync.aligned.m8n8.x4.shared.b16 {%0,%1,%2,%3}, [%4];"
                 : "=r"(r[0]), "=r"(r[1]), "=r"(r[2]), "=r"(r[3]) : "r"(addr));
}
__device__ __forceinline__ void ldsm4t(uint32_t* r, uint32_t addr) {
    asm volatile("ldmatrix.sync.aligned.m8n8.x4.trans.shared.b16 {%0,%1,%2,%3}, [%4];"
                 : "=r"(r[0]), "=r"(r[1]), "=r"(r[2]), "=r"(r[3]) : "r"(addr));
}
__device__ __forceinline__ void mma16816(float* c, const uint32_t* a, const uint32_t* b) {
    asm volatile(
        "mma.sync.aligned.m16n8k16.row.col.f32.f16.f16.f32 "
        "{%0,%1,%2,%3}, {%4,%5,%6,%7}, {%8,%9}, {%0,%1,%2,%3};"
        : "+f"(c[0]), "+f"(c[1]), "+f"(c[2]), "+f"(c[3])
        : "r"(a[0]), "r"(a[1]), "r"(a[2]), "r"(a[3]), "r"(b[0]), "r"(b[1]));
}
__device__ __forceinline__ void cpasync16(uint32_t dst, const void* src) {
    asm volatile("cp.async.cg.shared.global [%0], [%1], 16;" :: "r"(dst), "l"(src));
}
__device__ __forceinline__ void cpcommit() { asm volatile("cp.async.commit_group;"); }
__device__ __forceinline__ void cpwait0()  { asm volatile("cp.async.wait_group 0;"); }
__device__ __forceinline__ void cpwait1()  { asm volatile("cp.async.wait_group 1;"); }

__device__ __forceinline__ uint32_t f2h2(float a, float b) {
    return (uint32_t)__half_as_ushort(__float2half_rn(a)) |
           ((uint32_t)__half_as_ushort(__float2half_rn(b)) << 16);
}
__device__ __forceinline__ uint2 cvt4h(float4 v) {
    return make_uint2(f2h2(v.x, v.y), f2h2(v.z, v.w));
}

// ======================================================================
// KWM: Wm fp32 -> fp16 stream convert (runs on side stream under k1)
// ======================================================================
__global__ void kwm_cvt(const float* __restrict__ Wm) {
    size_t i = ((size_t)blockIdx.x * 256 + threadIdx.x) * 8;
    float4 v0 = *(const float4*)(Wm + i);
    float4 v1 = *(const float4*)(Wm + i + 4);
    *(uint4*)(g_WmH + i) = make_uint4(f2h2(v0.x, v0.y), f2h2(v0.z, v0.w),
                                      f2h2(v1.x, v1.y), f2h2(v1.z, v1.w));
}

// ======================================================================
// K0: catc[b,a] = W1_cat[a,:] . cat_emb[b,:]
// ======================================================================
__global__ void k0_catc(const float* __restrict__ W1, const float* __restrict__ cat) {
    int b = blockIdx.x;
    int warp = threadIdx.x >> 5, lane = threadIdx.x & 31;
    const float* cb = cat + b * DCAT;
    for (int a = warp; a < DA; a += 8) {
        const float* w = W1 + (size_t)a * D3 + D2;
        float s = 0.f;
        for (int d = lane; d < DCAT; d += 32) s += w[d] * cb[d];
        #pragma unroll
        for (int o = 16; o; o >>= 1) s += __shfl_xor_sync(0xffffffffu, s, o);
        if (lane == 0) g_catc[b * CATP + a] = s;
    }
}

// ======================================================================
// K0b: W1 -> fp16 [384][1024]; K0b2: W2 -> fp16 [32][384]; K0z: zero g_s2
// ======================================================================
__global__ void k0b_w1(const float* __restrict__ W1) {
    int i = blockIdx.x * 256 + threadIdx.x;
    int row = i >> 10, k = i & 1023;
    float v = (row < DA) ? W1[(size_t)row * D3 + k] : 0.f;
    g_W1H[i] = __float2half_rn(v);
}
__global__ void k0b2_w2(const float* __restrict__ W2) {
    int i = blockIdx.x * 256 + threadIdx.x;   // < 12288
    int r = i / 384, n = i - r * 384;
    float v = (r < RR && n < DA) ? W2[r * DA + n] : 0.f;
    g_W2H[i] = __float2half_rn(v);
}
__global__ void k0z_zero() {
    int i = blockIdx.x * 256 + threadIdx.x;   // < 491520
    *(float4*)(g_s2 + (size_t)i * 4) = make_float4(0.f, 0.f, 0.f, 0.f);
}

// ======================================================================
// K1: fp16 mma.sync GEMM, CTA tile 64(M) x 192(N), K chunks of 32.
//     3-stage cp.async pipeline (wait_group 1), 256 thr, 2 CTAs/SM.
//     A: enc fp32 -> fp16 in-register. Fused partial-s2 epilogue
//     (tensor core) -> atomicAdd into g_s2. grid (2 ntile, 1024 mtile).
// ======================================================================
#define K1_STG   16384
#define K1_B     4096
#define EP_STR   400                        // 192 halfs + pad, bytes
#define EP_W2    25600                      // 64*400
#define K1_SMEM  49152

__global__ void __launch_bounds__(256, 2) k1_s1s2(const float* __restrict__ enc) {
    extern __shared__ __align__(128) char sm[];
    uint32_t sb = smem_u32(sm);
    int t = threadIdx.x;
    int lane = t & 31, wid = t >> 5;
    int n0g = blockIdx.x * 192;
    int m0 = blockIdx.y * 64;
    int b = m0 >> 10;
    int wm = (wid >> 2) * 32;
    int wn = (wid & 3) * 48;

    float c[2][6][4];
    #pragma unroll
    for (int i = 0; i < 2; i++)
        #pragma unroll
        for (int j = 0; j < 6; j++)
            #pragma unroll
            for (int q = 0; q < 4; q++) c[i][j][q] = 0.f;

    int ar = t >> 2, ac = t & 3;
    const float* aptr = enc + (size_t)(m0 + ar) * D2 + ac * 8;
    uint32_t a_sts = (uint32_t)(ar * 64 + ((ac ^ ((ar >> 1) & 3)) << 4));

    // ---- prologue: stages 0 and 1 ----
    #pragma unroll
    for (int i = 0; i < 3; i++) {
        int idx = t + i * 256;
        int n = idx >> 2, ch = idx & 3;
        uint32_t doff = (uint32_t)(n * 64 + ((ch ^ ((n >> 1) & 3)) << 4));
        cpasync16(sb + K1_B + doff, g_W1H + (size_t)(n0g + n) * D2 + ch * 8);
    }
    cpcommit();
    #pragma unroll
    for (int i = 0; i < 3; i++) {
        int idx = t + i * 256;
        int n = idx >> 2, ch = idx & 3;
        uint32_t doff = (uint32_t)(n * 64 + ((ch ^ ((n >> 1) & 3)) << 4));
        cpasync16(sb + K1_STG + K1_B + doff, g_W1H + (size_t)(n0g + n) * D2 + 32 + ch * 8);
    }
    cpcommit();
    {
        float4 q0 = *(const float4*)(aptr);
        float4 q1 = *(const float4*)(aptr + 4);
        *(uint4*)(sm + a_sts) =
            make_uint4(f2h2(q0.x, q0.y), f2h2(q0.z, q0.w), f2h2(q1.x, q1.y), f2h2(q1.z, q1.w));
        q0 = *(const float4*)(aptr + 32);
        q1 = *(const float4*)(aptr + 36);
        *(uint4*)(sm + K1_STG + a_sts) =
            make_uint4(f2h2(q0.x, q0.y), f2h2(q0.z, q0.w), f2h2(q1.x, q1.y), f2h2(q1.z, q1.w));
    }

    float4 pa0, pa1;
    for (int cch = 0; cch < 32; cch++) {
        int s = cch - (cch / 3) * 3;
        uint32_t stg = (uint32_t)(s * K1_STG);
        cpwait1();
        __syncthreads();
        int nxt = cch + 2;
        if (nxt < 32) {
            int s2i = nxt - (nxt / 3) * 3;
            uint32_t stg2 = (uint32_t)(s2i * K1_STG);
            int k0n = nxt * 32;
            #pragma unroll
            for (int i = 0; i < 3; i++) {
                int idx = t + i * 256;
                int n = idx >> 2, ch = idx & 3;
                uint32_t doff = (uint32_t)(n * 64 + ((ch ^ ((n >> 1) & 3)) << 4));
                cpasync16(sb + stg2 + K1_B + doff,
                          g_W1H + (size_t)(n0g + n) * D2 + k0n + ch * 8);
            }
            pa0 = *(const float4*)(aptr + k0n);
            pa1 = *(const float4*)(aptr + k0n + 4);
        }
        cpcommit();
        #pragma unroll
        for (int kstep = 0; kstep < 2; kstep++) {
            uint32_t ah[2][4];
            #pragma unroll
            for (int mi = 0; mi < 2; mi++) {
                int r = wm + mi * 16 + (lane & 15);
                int ch = kstep * 2 + (lane >> 4);
                uint32_t off = (uint32_t)(r * 64 + ((ch ^ ((r >> 1) & 3)) << 4));
                ldsm4(ah[mi], sb + stg + off);
            }
            #pragma unroll
            for (int q = 0; q < 3; q++) {
                uint32_t bh[4];
                int n = wn + q * 16 + (lane & 7) + ((lane >> 4) << 3);
                int ch = kstep * 2 + ((lane >> 3) & 1);
                uint32_t off = (uint32_t)(n * 64 + ((ch ^ ((n >> 1) & 3)) << 4));
                ldsm4(bh, sb + stg + K1_B + off);
                #pragma unroll
                for (int mi = 0; mi < 2; mi++)
                    #pragma unroll
                    for (int j = 0; j < 2; j++)
                        mma16816(c[mi][q * 2 + j], ah[mi], &bh[j * 2]);
            }
        }
        if (nxt < 32) {
            int s2i = nxt - (nxt / 3) * 3;
            uint32_t stg2 = (uint32_t)(s2i * K1_STG);
            *(uint4*)(sm + stg2 + a_sts) =
                make_uint4(f2h2(pa0.x, pa0.y), f2h2(pa0.z, pa0.w),
                           f2h2(pa1.x, pa1.y), f2h2(pa1.z, pa1.w));
        }
    }

    // ---- fused partial-s2 epilogue (this CTA's 192 columns) ----
    cpwait0();
    __syncthreads();
    #pragma unroll
    for (int mi = 0; mi < 2; mi++) {
        int lr = wm + mi * 16 + (lane >> 2);
        #pragma unroll
        for (int cj = 0; cj < 6; cj++) {
            int ng = wn + cj * 8 + (lane & 3) * 2;
            float cc0 = g_catc[b * CATP + n0g + ng];
            float cc1 = g_catc[b * CATP + n0g + ng + 1];
            *(uint32_t*)(sm + lr * EP_STR + ng * 2) =
                f2h2(tanhf(c[mi][cj][0] + cc0), tanhf(c[mi][cj][1] + cc1));
            *(uint32_t*)(sm + (lr + 8) * EP_STR + ng * 2) =
                f2h2(tanhf(c[mi][cj][2] + cc0), tanhf(c[mi][cj][3] + cc1));
        }
    }
    #pragma unroll
    for (int i = 0; i < 3; i++) {
        int idx = t + i * 256;
        int r = idx / 24, seg = idx - r * 24;
        *(uint4*)(sm + EP_W2 + r * EP_STR + seg * 16) =
            *(const uint4*)(g_W2H + r * 384 + n0g + seg * 8);
    }
    __syncthreads();

    float c2[2][4];
    #pragma unroll
    for (int j = 0; j < 2; j++)
        #pragma unroll
        for (int q = 0; q < 4; q++) c2[j][q] = 0.f;
    int m0w = (wid & 3) * 16, rb = (wid >> 2) * 16;
    #pragma unroll
    for (int k0 = 0; k0 < 192; k0 += 16) {
        uint32_t aS[4], bW[4];
        ldsm4(aS, sb + (m0w + (lane & 15)) * EP_STR + (k0 + (lane >> 4) * 8) * 2);
        ldsm4(bW, sb + EP_W2 + (rb + (lane & 7) + ((lane >> 4) << 3)) * EP_STR
                      + (k0 + ((lane >> 3) & 1) * 8) * 2);
        mma16816(c2[0], aS, &bW[0]);
        mma16816(c2[1], aS, &bW[2]);
    }
    #pragma unroll
    for (int j = 0; j < 2; j++)
        #pragma unroll
        for (int q = 0; q < 4; q++) {
            int r = rb + j * 8 + (lane & 3) * 2 + (q & 1);
            int md = m0 + m0w + (lane >> 2) + (q >> 1) * 8;
            if (r < RR)
                atomicAdd(&g_s2[((size_t)b * RR + r) * SEQ + (md & 1023)], c2[j][q]);
        }
}

// ======================================================================
// K3: masked softmax; writes A (fp32 out) + probs fp16 (g_AH)
// ======================================================================
__global__ void k3_softmax(const int* __restrict__ len, float* __restrict__ outA) {
    __shared__ float sred[8];
    int br = blockIdx.x;
    int b = br / RR;
    int r = br - b * RR;
    int t = threadIdx.x;
    int lane = t & 31, warp = t >> 5;
    const float* src = g_s2 + (size_t)br * SEQ;
    int L = len[b];

    float4 v = *(const float4*)(src + t * 4);
    float vv[4] = {v.x, v.y, v.z, v.w};
    #pragma unroll
    for (int j = 0; j < 4; j++) if (t * 4 + j >= L) vv[j] = NEGV;

    float mx = fmaxf(fmaxf(vv[0], vv[1]), fmaxf(vv[2], vv[3]));
    #pragma unroll
    for (int o = 16; o; o >>= 1) mx = fmaxf(mx, __shfl_xor_sync(0xffffffffu, mx, o));
    if (lane == 0) sred[warp] = mx;
    __syncthreads();
    mx = sred[0];
    #pragma unroll
    for (int w = 1; w < 8; w++) mx = fmaxf(mx, sred[w]);

    float e[4], s = 0.f;
    #pragma unroll
    for (int j = 0; j < 4; j++) { e[j] = __expf(vv[j] - mx); s += e[j]; }
    #pragma unroll
    for (int o = 16; o; o >>= 1) s += __shfl_xor_sync(0xffffffffu, s, o);
    __syncthreads();
    if (lane == 0) sred[warp] = s;
    __syncthreads();
    s = 0.f;
    #pragma unroll
    for (int w = 0; w < 8; w++) s += sred[w];
    float inv = 1.f / s;

    float p0 = e[0] * inv, p1 = e[1] * inv, p2 = e[2] * inv, p3 = e[3] * inv;
    *(float4*)(outA + (size_t)br * SEQ + t * 4) = make_float4(p0, p1, p2, p3);
    *(uint2*)(g_AH + ((size_t)b * 32 + r) * SEQ + t * 4) =
        make_uint2(f2h2(p0, p1), f2h2(p2, p3));
}

// ======================================================================
// K4: M_enc = A @ enc via fp16 tensor cores; enc fp32 converted on STS.
// ======================================================================
#define K4_ENCSTR 272
#define K4_PRBSTR 80
#define K4_PRB   8704
#define K4_STGSZ 11264

__global__ void __launch_bounds__(256) k4_mgemm(const float* __restrict__ enc) {
    __shared__ __align__(128) char sm4[2 * K4_STGSZ];
    uint32_t sb4 = smem_u32(sm4);
    int t = threadIdx.x;
    int lane = t & 31, wid = t >> 5;
    int dtile = blockIdx.x, b = blockIdx.y;
    const float* Eb = enc + (size_t)b * SEQ * D2 + dtile * 128;
    const __half* Ap = g_AH + ((size_t)b * 32 + (t >> 3)) * SEQ + (t & 7) * 4;

    float c[4][4];
    #pragma unroll
    for (int i = 0; i < 4; i++)
        #pragma unroll
        for (int q = 0; q < 4; q++) c[i][q] = 0.f;

    float4 pe[4];
    uint2 pp = *(const uint2*)(Ap);
    #pragma unroll
    for (int li = 0; li < 4; li++) {
        int idx = t + li * 256;
        pe[li] = *(const float4*)(Eb + (size_t)(idx >> 5) * D2 + (idx & 31) * 4);
    }

    for (int n0 = 0; n0 < SEQ; n0 += 32) {
        int s = (n0 >> 5) & 1;
        uint32_t base = (uint32_t)(s * K4_STGSZ);
        *(uint2*)(sm4 + base + K4_PRB + (t >> 3) * K4_PRBSTR + (t & 7) * 8) = pp;
        #pragma unroll
        for (int li = 0; li < 4; li++) {
            int idx = t + li * 256;
            *(uint2*)(sm4 + base + (idx >> 5) * K4_ENCSTR + (idx & 31) * 8) = cvt4h(pe[li]);
        }
        __syncthreads();
        if (n0 + 32 < SEQ) {
            pp = *(const uint2*)(Ap + n0 + 32);
            #pragma unroll
            for (int li = 0; li < 4; li++) {
                int idx = t + li * 256;
                pe[li] = *(const float4*)(Eb + (size_t)(n0 + 32 + (idx >> 5)) * D2 + (idx & 31) * 4);
            }
        }
        #pragma unroll
        for (int ks = 0; ks < 2; ks++) {
            int kk = ks * 16;
            uint32_t ae[4], bp[8];
            ldsm4t(ae, sb4 + base + (kk + (lane & 7) + ((lane >> 4) << 3)) * K4_ENCSTR
                          + (wid * 16 + ((lane >> 3) & 1) * 8) * 2);
            uint32_t bpr = sb4 + base + K4_PRB
                          + ((lane & 7) + ((lane >> 4) << 3)) * K4_PRBSTR
                          + kk * 2 + ((lane >> 3) & 1) * 16;
            ldsm4(bp, bpr);
            ldsm4(bp + 4, bpr + 16 * K4_PRBSTR);
            mma16816(c[0], ae, &bp[0]);
            mma16816(c[1], ae, &bp[2]);
            mma16816(c[2], ae, &bp[4]);
            mma16816(c[3], ae, &bp[6]);
        }
    }

    #pragma unroll
    for (int nj = 0; nj < 4; nj++)
        #pragma unroll
        for (int q = 0; q < 4; q++) {
            int r = nj * 8 + (lane & 3) * 2 + (q & 1);
            if (r < RR) {
                int d = dtile * 128 + wid * 16 + (lane >> 2) + (q >> 1) * 8;
                g_BM[(size_t)b * KMLP + (size_t)r * D3 + d] = __float2half_rn(c[nj][q]);
            }
        }
}

// ======================================================================
// K5b: fill cat part of BM (exact: softmax rows sum to 1)
// ======================================================================
__global__ void k5b_cat(const float* __restrict__ cat) {
    int idx = (blockIdx.x * 256 + threadIdx.x) * 4;
    int b = idx / (RR * DCAT);
    int rem = idx - b * RR * DCAT;
    int r = rem >> 9, d = rem & 511;
    float4 v = *(const float4*)(cat + (size_t)b * DCAT + d);
    size_t o = (size_t)b * KMLP + (size_t)r * D3 + D2 + d;
    *(uint2*)(g_BM + o) = cvt4h(v);
}

// ======================================================================
// K6: fp16 mma.sync split-K GEMM; BOTH operands cp.async fp16 (Wm from
//     g_WmH), double-buffered, 2 CTAs/SM. No in-loop conversion.
// ======================================================================
#define K6_STG 24576
#define K6_W   0
#define K6_B   16384
#define K6_SMEM 49152

__global__ void __launch_bounds__(256, 2) k6_mlp() {
    extern __shared__ __align__(128) char sm[];
    uint32_t sb = smem_u32(sm);
    int t = threadIdx.x;
    int lane = t & 31, wid = t >> 5;
    int j0 = blockIdx.x * 128;
    int ks = blockIdx.y;
    int kbeg = ks * KCHUNK;
    int wj = (wid >> 2) * 64;
    int wb = (wid & 3) * 16;

    float c[4][2][4];
    #pragma unroll
    for (int i = 0; i < 4; i++)
        #pragma unroll
        for (int j = 0; j < 2; j++)
            #pragma unroll
            for (int q = 0; q < 4; q++) c[i][j][q] = 0.f;

    // prologue: stage 0 (W 16KB + B 8KB)
    #pragma unroll
    for (int i = 0; i < 4; i++) {
        int idx = t + i * 256;               // < 1024
        int row = idx >> 3, seg = idx & 7;
        uint32_t doff = (uint32_t)(row * 128 + ((seg * 16) ^ ((row & 7) << 4)));
        cpasync16(sb + K6_W + doff, g_WmH + (size_t)(j0 + row) * KMLP + kbeg + seg * 8);
    }
    #pragma unroll
    for (int i = 0; i < 2; i++) {
        int idx = t + i * 256;               // < 512
        int row = idx >> 3, seg = idx & 7;
        uint32_t doff = (uint32_t)(row * 128 + ((seg * 16) ^ ((row & 7) << 4)));
        cpasync16(sb + K6_B + doff, g_BM + (size_t)row * KMLP + kbeg + seg * 8);
    }
    cpcommit();

    int arow_l = lane & 15;
    int acol_l = (lane >> 4) * 16;
    int brow_l = (lane & 7) + ((lane >> 4) << 3);
    int bcol_l = ((lane >> 3) & 1) * 16;

    for (int cch = 0; cch < NCH6; cch++) {
        int s = cch & 1;
        uint32_t stg = (uint32_t)(s * K6_STG);
        cpwait0();
        __syncthreads();
        if (cch < NCH6 - 1) {
            uint32_t stg1 = (uint32_t)((s ^ 1) * K6_STG);
            int k0n = kbeg + (cch + 1) * 64;
            #pragma unroll
            for (int i = 0; i < 4; i++) {
                int idx = t + i * 256;
                int row = idx >> 3, seg = idx & 7;
                uint32_t doff = (uint32_t)(row * 128 + ((seg * 16) ^ ((row & 7) << 4)));
                cpasync16(sb + stg1 + K6_W + doff,
                          g_WmH + (size_t)(j0 + row) * KMLP + k0n + seg * 8);
            }
            #pragma unroll
            for (int i = 0; i < 2; i++) {
                int idx = t + i * 256;
                int row = idx >> 3, seg = idx & 7;
                uint32_t doff = (uint32_t)(row * 128 + ((seg * 16) ^ ((row & 7) << 4)));
                cpasync16(sb + stg1 + K6_B + doff, g_BM + (size_t)row * KMLP + k0n + seg * 8);
            }
            cpcommit();
        }
        #pragma unroll
        for (int ksp = 0; ksp < 4; ksp++) {
            int kb = ksp * 32;
            uint32_t ah[4][4], bh[4];
            #pragma unroll
            for (int mi = 0; mi < 4; mi++) {
                int row = wj + mi * 16 + arow_l;
                uint32_t off = (uint32_t)(row * 128 + ((kb + acol_l) ^ ((row & 7) << 4)));
                ldsm4(ah[mi], sb + stg + K6_W + off);
            }
            {
                int row = wb + brow_l;
                uint32_t off = (uint32_t)(row * 128 + ((kb + bcol_l) ^ ((row & 7) << 4)));
                ldsm4(bh, sb + stg + K6_B + off);
            }
            #pragma unroll
            for (int mi = 0; mi < 4; mi++)
                #pragma unroll
                for (int j = 0; j < 2; j++)
                    mma16816(c[mi][j], ah[mi], &bh[j * 2]);
        }
    }

    #pragma unroll
    for (int mi = 0; mi < 4; mi++) {
        int jr = j0 + wj + mi * 16 + (lane >> 2);
        #pragma unroll
        for (int j = 0; j < 2; j++) {
            int bc = wb + j * 8 + (lane & 3) * 2;
            float* d0 = g_part + ((size_t)ks * MLPD + jr) * BATCH + bc;
            float* d1 = g_part + ((size_t)ks * MLPD + jr + 8) * BATCH + bc;
            d0[0] = c[mi][j][0]; d0[1] = c[mi][j][1];
            d1[0] = c[mi][j][2]; d1[1] = c[mi][j][3];
        }
    }
}

// ======================================================================
// K7: reduce split-K + bias -> d_out
// ======================================================================
__global__ void k7_reduce(const float* __restrict__ bias, float* __restrict__ out) {
    int idx = blockIdx.x * 256 + threadIdx.x;
    int j = idx >> 6, b = idx & 63;
    float s = bias[j];
    #pragma unroll
    for (int ks = 0; ks < KSPLIT; ks++)
        s += g_part[((size_t)ks * MLPD + j) * BATCH + b];
    out[(size_t)b * MLPD + j] = s;
}

// ======================================================================
extern "C" void kernel_launch(void* const* d_in, const int* in_sizes, int n_in,
                              void* d_out, int out_size) {
    const float* enc = nullptr;
    const int*   len = nullptr;
    const float* cat = nullptr;
    const float* W1 = nullptr;
    const float* W2 = nullptr;
    const float* Wm = nullptr;
    const float* bm = nullptr;
    for (int i = 0; i < n_in; i++) {
        switch (in_sizes[i]) {
            case 67108864: enc = (const float*)d_in[i]; break;
            case 64:       len = (const int*)d_in[i];   break;
            case 32768:    cat = (const float*)d_in[i]; break;
            case 537600:   W1  = (const float*)d_in[i]; break;
            case 10500:    W2  = (const float*)d_in[i]; break;
            case 94371840: Wm  = (const float*)d_in[i]; break;
            case 2048:     bm  = (const float*)d_in[i]; break;
            default: break;
        }
    }
    float* outf = (float*)d_out;
    float* outO = outf;
    float* outA = outf + BATCH * MLPD;

    cudaFuncSetAttribute(k1_s1s2, cudaFuncAttributeMaxDynamicSharedMemorySize, K1_SMEM);
    cudaFuncSetAttribute(k6_mlp, cudaFuncAttributeMaxDynamicSharedMemorySize, K6_SMEM);

    // side-stream fork: convert Wm -> fp16 concurrently with main chain
    cudaStream_t s2 = 0;
    cudaEvent_t e1 = 0, e2 = 0;
    bool forked = false;
    if (cudaStreamCreateWithFlags(&s2, cudaStreamNonBlocking) == cudaSuccess) {
        if (cudaEventCreateWithFlags(&e1, cudaEventDisableTiming) == cudaSuccess &&
            cudaEventCreateWithFlags(&e2, cudaEventDisableTiming) == cudaSuccess)
            forked = true;
    }

    if (forked) {
        cudaEventRecord(e1, 0);
        cudaStreamWaitEvent(s2, e1, 0);
        kwm_cvt<<<46080, 256, 0, s2>>>(Wm);
        cudaEventRecord(e2, s2);
    } else {
        kwm_cvt<<<46080, 256>>>(Wm);
    }

    k0_catc   <<<BATCH, 256>>>(W1, cat);
    k0b_w1    <<<(NW1 * D2) / 256, 256>>>(W1);
    k0b2_w2   <<<48, 256>>>(W2);
    k0z_zero  <<<1920, 256>>>();
    k1_s1s2   <<<dim3(2, ROWS / 64), 256, K1_SMEM>>>(enc);
    k3_softmax<<<BATCH * RR, 256>>>(len, outA);
    k4_mgemm  <<<dim3(8, BATCH), 256>>>(enc);
    k5b_cat   <<<(BATCH * RR * DCAT) / 1024, 256>>>(cat);

    if (forked) cudaStreamWaitEvent(0, e2, 0);
    k6_mlp    <<<dim3(MLPD / 128, KSPLIT), 256, K6_SMEM>>>();
    k7_reduce <<<(BATCH * MLPD) / 256, 256>>>(bm, outO);
}

// round 17
// speedup vs baseline: 1.5001x; 1.5001x over previous
#include <cuda_runtime.h>
#include <cuda_fp16.h>
#include <math.h>
#include <stdint.h>

#define BATCH 64
#define SEQ   1024
#define D2    1024
#define DCAT  512
#define D3    1536
#define DA    350
#define CATP  384
#define NW1   384
#define RR    30
#define MLPD  2048
#define KMLP  46080
#define ROWS  65536
#define NEGV  (-1e9f)
#define KSPLIT 18
#define KCHUNK 2560
#define NCH6   40

// ---------------- scratch ----------------
__device__ float g_catc[BATCH * CATP];
__device__ float g_s2[BATCH * RR * SEQ];
__device__ __align__(128) __half g_W1H[NW1 * D2];
__device__ __align__(128) __half g_W2H[32 * 384];
__device__ __align__(128) __half g_AH[BATCH * 32 * SEQ];
__device__ __align__(128) __half g_BM[BATCH * KMLP];

// ---------------- helpers ----------------
__device__ __forceinline__ uint32_t smem_u32(const void* p) {
    uint32_t r;
    asm("{ .reg .u64 t; cvta.to.shared.u64 t, %1; cvt.u32.u64 %0, t; }" : "=r"(r) : "l"(p));
    return r;
}
__device__ __forceinline__ void ldsm4(uint32_t* r, uint32_t addr) {
    asm volatile("ldmatrix.sync.aligned.m8n8.x4.shared.b16 {%0,%1,%2,%3}, [%4];"
                 : "=r"(r[0]), "=r"(r[1]), "=r"(r[2]), "=r"(r[3]) : "r"(addr));
}
__device__ __forceinline__ void ldsm4t(uint32_t* r, uint32_t addr) {
    asm volatile("ldmatrix.sync.aligned.m8n8.x4.trans.shared.b16 {%0,%1,%2,%3}, [%4];"
                 : "=r"(r[0]), "=r"(r[1]), "=r"(r[2]), "=r"(r[3]) : "r"(addr));
}
__device__ __forceinline__ void mma16816(float* c, const uint32_t* a, const uint32_t* b) {
    asm volatile(
        "mma.sync.aligned.m16n8k16.row.col.f32.f16.f16.f32 "
        "{%0,%1,%2,%3}, {%4,%5,%6,%7}, {%8,%9}, {%0,%1,%2,%3};"
        : "+f"(c[0]), "+f"(c[1]), "+f"(c[2]), "+f"(c[3])
        : "r"(a[0]), "r"(a[1]), "r"(a[2]), "r"(a[3]), "r"(b[0]), "r"(b[1]));
}
__device__ __forceinline__ void cpasync16(uint32_t dst, const void* src) {
    asm volatile("cp.async.cg.shared.global [%0], [%1], 16;" :: "r"(dst), "l"(src));
}
__device__ __forceinline__ void cpcommit() { asm volatile("cp.async.commit_group;"); }
__device__ __forceinline__ void cpwait0()  { asm volatile("cp.async.wait_group 0;"); }
__device__ __forceinline__ void cpwait1()  { asm volatile("cp.async.wait_group 1;"); }

__device__ __forceinline__ uint32_t f2h2(float a, float b) {
    return (uint32_t)__half_as_ushort(__float2half_rn(a)) |
           ((uint32_t)__half_as_ushort(__float2half_rn(b)) << 16);
}
__device__ __forceinline__ uint2 cvt4h(float4 v) {
    return make_uint2(f2h2(v.x, v.y), f2h2(v.z, v.w));
}

// ======================================================================
// KA: merged prep — W1 cvt | W2 cvt | zero g_s2 | bias->out | catc
//     block ranges: [0,1536) W1, [1536,1584) W2, [1584,3504) zero,
//                   [3504,4016) bias, [4016,4080) catc
// ======================================================================
__global__ void kA_prep(const float* __restrict__ W1, const float* __restrict__ W2,
                        const float* __restrict__ cat, const float* __restrict__ bias,
                        float* __restrict__ outO) {
    int blk = blockIdx.x, t = threadIdx.x;
    if (blk < 1536) {
        int i = blk * 256 + t;
        int row = i >> 10, k = i & 1023;
        float v = (row < DA) ? W1[(size_t)row * D3 + k] : 0.f;
        g_W1H[i] = __float2half_rn(v);
    } else if (blk < 1584) {
        int i = (blk - 1536) * 256 + t;
        int r = i / 384, n = i - r * 384;
        float v = (r < RR && n < DA) ? W2[r * DA + n] : 0.f;
        g_W2H[i] = __float2half_rn(v);
    } else if (blk < 3504) {
        int i = (blk - 1584) * 256 + t;
        *(float4*)(g_s2 + (size_t)i * 4) = make_float4(0.f, 0.f, 0.f, 0.f);
    } else if (blk < 4016) {
        int i = (blk - 3504) * 256 + t;          // < 131072
        outO[i] = bias[i & (MLPD - 1)];
    } else {
        int b = blk - 4016;
        int warp = t >> 5, lane = t & 31;
        const float* cb = cat + b * DCAT;
        for (int a = warp; a < DA; a += 8) {
            const float* w = W1 + (size_t)a * D3 + D2;
            float s = 0.f;
            for (int d = lane; d < DCAT; d += 32) s += w[d] * cb[d];
            #pragma unroll
            for (int o = 16; o; o >>= 1) s += __shfl_xor_sync(0xffffffffu, s, o);
            if (lane == 0) g_catc[b * CATP + a] = s;
        }
    }
}

// ======================================================================
// K1: fp16 mma.sync GEMM, CTA tile 64(M) x 192(N), K chunks of 32.
//     3-stage cp.async pipeline, 256 thr, 2 CTAs/SM. Fused partial-s2
//     epilogue -> atomicAdd into g_s2. grid (2 ntile, 1024 mtile).
// ======================================================================
#define K1_STG   16384
#define K1_B     4096
#define EP_STR   400
#define EP_W2    25600
#define K1_SMEM  49152

__global__ void __launch_bounds__(256, 2) k1_s1s2(const float* __restrict__ enc) {
    extern __shared__ __align__(128) char sm[];
    uint32_t sb = smem_u32(sm);
    int t = threadIdx.x;
    int lane = t & 31, wid = t >> 5;
    int n0g = blockIdx.x * 192;
    int m0 = blockIdx.y * 64;
    int b = m0 >> 10;
    int wm = (wid >> 2) * 32;
    int wn = (wid & 3) * 48;

    float c[2][6][4];
    #pragma unroll
    for (int i = 0; i < 2; i++)
        #pragma unroll
        for (int j = 0; j < 6; j++)
            #pragma unroll
            for (int q = 0; q < 4; q++) c[i][j][q] = 0.f;

    int ar = t >> 2, ac = t & 3;
    const float* aptr = enc + (size_t)(m0 + ar) * D2 + ac * 8;
    uint32_t a_sts = (uint32_t)(ar * 64 + ((ac ^ ((ar >> 1) & 3)) << 4));

    #pragma unroll
    for (int i = 0; i < 3; i++) {
        int idx = t + i * 256;
        int n = idx >> 2, ch = idx & 3;
        uint32_t doff = (uint32_t)(n * 64 + ((ch ^ ((n >> 1) & 3)) << 4));
        cpasync16(sb + K1_B + doff, g_W1H + (size_t)(n0g + n) * D2 + ch * 8);
    }
    cpcommit();
    #pragma unroll
    for (int i = 0; i < 3; i++) {
        int idx = t + i * 256;
        int n = idx >> 2, ch = idx & 3;
        uint32_t doff = (uint32_t)(n * 64 + ((ch ^ ((n >> 1) & 3)) << 4));
        cpasync16(sb + K1_STG + K1_B + doff, g_W1H + (size_t)(n0g + n) * D2 + 32 + ch * 8);
    }
    cpcommit();
    {
        float4 q0 = *(const float4*)(aptr);
        float4 q1 = *(const float4*)(aptr + 4);
        *(uint4*)(sm + a_sts) =
            make_uint4(f2h2(q0.x, q0.y), f2h2(q0.z, q0.w), f2h2(q1.x, q1.y), f2h2(q1.z, q1.w));
        q0 = *(const float4*)(aptr + 32);
        q1 = *(const float4*)(aptr + 36);
        *(uint4*)(sm + K1_STG + a_sts) =
            make_uint4(f2h2(q0.x, q0.y), f2h2(q0.z, q0.w), f2h2(q1.x, q1.y), f2h2(q1.z, q1.w));
    }

    float4 pa0, pa1;
    for (int cch = 0; cch < 32; cch++) {
        int s = cch - (cch / 3) * 3;
        uint32_t stg = (uint32_t)(s * K1_STG);
        cpwait1();
        __syncthreads();
        int nxt = cch + 2;
        if (nxt < 32) {
            int s2i = nxt - (nxt / 3) * 3;
            uint32_t stg2 = (uint32_t)(s2i * K1_STG);
            int k0n = nxt * 32;
            #pragma unroll
            for (int i = 0; i < 3; i++) {
                int idx = t + i * 256;
                int n = idx >> 2, ch = idx & 3;
                uint32_t doff = (uint32_t)(n * 64 + ((ch ^ ((n >> 1) & 3)) << 4));
                cpasync16(sb + stg2 + K1_B + doff,
                          g_W1H + (size_t)(n0g + n) * D2 + k0n + ch * 8);
            }
            pa0 = *(const float4*)(aptr + k0n);
            pa1 = *(const float4*)(aptr + k0n + 4);
        }
        cpcommit();
        #pragma unroll
        for (int kstep = 0; kstep < 2; kstep++) {
            uint32_t ah[2][4];
            #pragma unroll
            for (int mi = 0; mi < 2; mi++) {
                int r = wm + mi * 16 + (lane & 15);
                int ch = kstep * 2 + (lane >> 4);
                uint32_t off = (uint32_t)(r * 64 + ((ch ^ ((r >> 1) & 3)) << 4));
                ldsm4(ah[mi], sb + stg + off);
            }
            #pragma unroll
            for (int q = 0; q < 3; q++) {
                uint32_t bh[4];
                int n = wn + q * 16 + (lane & 7) + ((lane >> 4) << 3);
                int ch = kstep * 2 + ((lane >> 3) & 1);
                uint32_t off = (uint32_t)(n * 64 + ((ch ^ ((n >> 1) & 3)) << 4));
                ldsm4(bh, sb + stg + K1_B + off);
                #pragma unroll
                for (int mi = 0; mi < 2; mi++)
                    #pragma unroll
                    for (int j = 0; j < 2; j++)
                        mma16816(c[mi][q * 2 + j], ah[mi], &bh[j * 2]);
            }
        }
        if (nxt < 32) {
            int s2i = nxt - (nxt / 3) * 3;
            uint32_t stg2 = (uint32_t)(s2i * K1_STG);
            *(uint4*)(sm + stg2 + a_sts) =
                make_uint4(f2h2(pa0.x, pa0.y), f2h2(pa0.z, pa0.w),
                           f2h2(pa1.x, pa1.y), f2h2(pa1.z, pa1.w));
        }
    }

    cpwait0();
    __syncthreads();
    #pragma unroll
    for (int mi = 0; mi < 2; mi++) {
        int lr = wm + mi * 16 + (lane >> 2);
        #pragma unroll
        for (int cj = 0; cj < 6; cj++) {
            int ng = wn + cj * 8 + (lane & 3) * 2;
            float cc0 = g_catc[b * CATP + n0g + ng];
            float cc1 = g_catc[b * CATP + n0g + ng + 1];
            *(uint32_t*)(sm + lr * EP_STR + ng * 2) =
                f2h2(tanhf(c[mi][cj][0] + cc0), tanhf(c[mi][cj][1] + cc1));
            *(uint32_t*)(sm + (lr + 8) * EP_STR + ng * 2) =
                f2h2(tanhf(c[mi][cj][2] + cc0), tanhf(c[mi][cj][3] + cc1));
        }
    }
    #pragma unroll
    for (int i = 0; i < 3; i++) {
        int idx = t + i * 256;
        int r = idx / 24, seg = idx - r * 24;
        *(uint4*)(sm + EP_W2 + r * EP_STR + seg * 16) =
            *(const uint4*)(g_W2H + r * 384 + n0g + seg * 8);
    }
    __syncthreads();

    float c2[2][4];
    #pragma unroll
    for (int j = 0; j < 2; j++)
        #pragma unroll
        for (int q = 0; q < 4; q++) c2[j][q] = 0.f;
    int m0w = (wid & 3) * 16, rb = (wid >> 2) * 16;
    #pragma unroll
    for (int k0 = 0; k0 < 192; k0 += 16) {
        uint32_t aS[4], bW[4];
        ldsm4(aS, sb + (m0w + (lane & 15)) * EP_STR + (k0 + (lane >> 4) * 8) * 2);
        ldsm4(bW, sb + EP_W2 + (rb + (lane & 7) + ((lane >> 4) << 3)) * EP_STR
                      + (k0 + ((lane >> 3) & 1) * 8) * 2);
        mma16816(c2[0], aS, &bW[0]);
        mma16816(c2[1], aS, &bW[2]);
    }
    #pragma unroll
    for (int j = 0; j < 2; j++)
        #pragma unroll
        for (int q = 0; q < 4; q++) {
            int r = rb + j * 8 + (lane & 3) * 2 + (q & 1);
            int md = m0 + m0w + (lane >> 2) + (q >> 1) * 8;
            if (r < RR)
                atomicAdd(&g_s2[((size_t)b * RR + r) * SEQ + (md & 1023)], c2[j][q]);
        }
}

// ======================================================================
// K3: masked softmax; writes A (fp32 out) + probs fp16 (g_AH)
// ======================================================================
__global__ void k3_softmax(const int* __restrict__ len, float* __restrict__ outA) {
    __shared__ float sred[8];
    int br = blockIdx.x;
    int b = br / RR;
    int r = br - b * RR;
    int t = threadIdx.x;
    int lane = t & 31, warp = t >> 5;
    const float* src = g_s2 + (size_t)br * SEQ;
    int L = len[b];

    float4 v = *(const float4*)(src + t * 4);
    float vv[4] = {v.x, v.y, v.z, v.w};
    #pragma unroll
    for (int j = 0; j < 4; j++) if (t * 4 + j >= L) vv[j] = NEGV;

    float mx = fmaxf(fmaxf(vv[0], vv[1]), fmaxf(vv[2], vv[3]));
    #pragma unroll
    for (int o = 16; o; o >>= 1) mx = fmaxf(mx, __shfl_xor_sync(0xffffffffu, mx, o));
    if (lane == 0) sred[warp] = mx;
    __syncthreads();
    mx = sred[0];
    #pragma unroll
    for (int w = 1; w < 8; w++) mx = fmaxf(mx, sred[w]);

    float e[4], s = 0.f;
    #pragma unroll
    for (int j = 0; j < 4; j++) { e[j] = __expf(vv[j] - mx); s += e[j]; }
    #pragma unroll
    for (int o = 16; o; o >>= 1) s += __shfl_xor_sync(0xffffffffu, s, o);
    __syncthreads();
    if (lane == 0) sred[warp] = s;
    __syncthreads();
    s = 0.f;
    #pragma unroll
    for (int w = 0; w < 8; w++) s += sred[w];
    float inv = 1.f / s;

    float p0 = e[0] * inv, p1 = e[1] * inv, p2 = e[2] * inv, p3 = e[3] * inv;
    *(float4*)(outA + (size_t)br * SEQ + t * 4) = make_float4(p0, p1, p2, p3);
    *(uint2*)(g_AH + ((size_t)b * 32 + r) * SEQ + t * 4) =
        make_uint2(f2h2(p0, p1), f2h2(p2, p3));
}

// ======================================================================
// K4: M_enc = A @ enc via fp16 tensor cores; enc fp32 converted on STS.
// ======================================================================
#define K4_ENCSTR 272
#define K4_PRBSTR 80
#define K4_PRB   8704
#define K4_STGSZ 11264

__global__ void __launch_bounds__(256) k4_mgemm(const float* __restrict__ enc) {
    __shared__ __align__(128) char sm4[2 * K4_STGSZ];
    uint32_t sb4 = smem_u32(sm4);
    int t = threadIdx.x;
    int lane = t & 31, wid = t >> 5;
    int dtile = blockIdx.x, b = blockIdx.y;
    const float* Eb = enc + (size_t)b * SEQ * D2 + dtile * 128;
    const __half* Ap = g_AH + ((size_t)b * 32 + (t >> 3)) * SEQ + (t & 7) * 4;

    float c[4][4];
    #pragma unroll
    for (int i = 0; i < 4; i++)
        #pragma unroll
        for (int q = 0; q < 4; q++) c[i][q] = 0.f;

    float4 pe[4];
    uint2 pp = *(const uint2*)(Ap);
    #pragma unroll
    for (int li = 0; li < 4; li++) {
        int idx = t + li * 256;
        pe[li] = *(const float4*)(Eb + (size_t)(idx >> 5) * D2 + (idx & 31) * 4);
    }

    for (int n0 = 0; n0 < SEQ; n0 += 32) {
        int s = (n0 >> 5) & 1;
        uint32_t base = (uint32_t)(s * K4_STGSZ);
        *(uint2*)(sm4 + base + K4_PRB + (t >> 3) * K4_PRBSTR + (t & 7) * 8) = pp;
        #pragma unroll
        for (int li = 0; li < 4; li++) {
            int idx = t + li * 256;
            *(uint2*)(sm4 + base + (idx >> 5) * K4_ENCSTR + (idx & 31) * 8) = cvt4h(pe[li]);
        }
        __syncthreads();
        if (n0 + 32 < SEQ) {
            pp = *(const uint2*)(Ap + n0 + 32);
            #pragma unroll
            for (int li = 0; li < 4; li++) {
                int idx = t + li * 256;
                pe[li] = *(const float4*)(Eb + (size_t)(n0 + 32 + (idx >> 5)) * D2 + (idx & 31) * 4);
            }
        }
        #pragma unroll
        for (int ks = 0; ks < 2; ks++) {
            int kk = ks * 16;
            uint32_t ae[4], bp[8];
            ldsm4t(ae, sb4 + base + (kk + (lane & 7) + ((lane >> 4) << 3)) * K4_ENCSTR
                          + (wid * 16 + ((lane >> 3) & 1) * 8) * 2);
            uint32_t bpr = sb4 + base + K4_PRB
                          + ((lane & 7) + ((lane >> 4) << 3)) * K4_PRBSTR
                          + kk * 2 + ((lane >> 3) & 1) * 16;
            ldsm4(bp, bpr);
            ldsm4(bp + 4, bpr + 16 * K4_PRBSTR);
            mma16816(c[0], ae, &bp[0]);
            mma16816(c[1], ae, &bp[2]);
            mma16816(c[2], ae, &bp[4]);
            mma16816(c[3], ae, &bp[6]);
        }
    }

    #pragma unroll
    for (int nj = 0; nj < 4; nj++)
        #pragma unroll
        for (int q = 0; q < 4; q++) {
            int r = nj * 8 + (lane & 3) * 2 + (q & 1);
            if (r < RR) {
                int d = dtile * 128 + wid * 16 + (lane >> 2) + (q >> 1) * 8;
                g_BM[(size_t)b * KMLP + (size_t)r * D3 + d] = __float2half_rn(c[nj][q]);
            }
        }
}

// ======================================================================
// K5b: fill cat part of BM (exact: softmax rows sum to 1)
// ======================================================================
__global__ void k5b_cat(const float* __restrict__ cat) {
    int idx = (blockIdx.x * 256 + threadIdx.x) * 4;
    int b = idx / (RR * DCAT);
    int rem = idx - b * RR * DCAT;
    int r = rem >> 9, d = rem & 511;
    float4 v = *(const float4*)(cat + (size_t)b * DCAT + d);
    size_t o = (size_t)b * KMLP + (size_t)r * D3 + D2 + d;
    *(uint2*)(g_BM + o) = cvt4h(v);
}

// ======================================================================
// K6: fp16 mma.sync split-K GEMM, 3-stage pipeline (wait_group 1),
//     2 CTAs/SM; epilogue atomicAdd into out (bias pre-loaded).
// ======================================================================
#define K6_STG 24576
#define K6_W   0
#define K6_B   16384
#define K6_SMEM 73728

__global__ void __launch_bounds__(256, 2) k6_mlp(const float* __restrict__ Wm,
                                                 float* __restrict__ outO) {
    extern __shared__ __align__(128) char sm[];
    uint32_t sb = smem_u32(sm);
    int t = threadIdx.x;
    int lane = t & 31, wid = t >> 5;
    int j0 = blockIdx.x * 128;
    int ks = blockIdx.y;
    int kbeg = ks * KCHUNK;
    int wj = (wid >> 2) * 64;
    int wb = (wid & 3) * 16;

    float c[4][2][4];
    #pragma unroll
    for (int i = 0; i < 4; i++)
        #pragma unroll
        for (int j = 0; j < 2; j++)
            #pragma unroll
            for (int q = 0; q < 4; q++) c[i][j][q] = 0.f;

    float4 wreg[8];
    // ---- prologue: B chunks 0,1 via cp.async; W chunks 0,1 via regs ----
    #pragma unroll
    for (int i = 0; i < 2; i++) {
        int idx = t + i * 256;
        int row = idx >> 3, seg = idx & 7;
        uint32_t doff = (uint32_t)(row * 128 + ((seg * 16) ^ ((row & 7) << 4)));
        cpasync16(sb + K6_B + doff, g_BM + (size_t)row * KMLP + kbeg + seg * 8);
    }
    cpcommit();
    #pragma unroll
    for (int i = 0; i < 2; i++) {
        int idx = t + i * 256;
        int row = idx >> 3, seg = idx & 7;
        uint32_t doff = (uint32_t)(row * 128 + ((seg * 16) ^ ((row & 7) << 4)));
        cpasync16(sb + K6_STG + K6_B + doff, g_BM + (size_t)row * KMLP + kbeg + 64 + seg * 8);
    }
    cpcommit();
    #pragma unroll
    for (int li = 0; li < 8; li++) {
        int idx = t + li * 256;
        wreg[li] = *(const float4*)(Wm + (size_t)(j0 + (idx >> 4)) * KMLP + kbeg + (idx & 15) * 4);
    }
    #pragma unroll
    for (int li = 0; li < 8; li++) {
        int idx = t + li * 256;
        int row = idx >> 4, seg = idx & 15;
        uint32_t byte = (uint32_t)(row * 128 + ((seg * 8) ^ ((row & 7) << 4)));
        *(uint2*)(sm + K6_W + byte) = cvt4h(wreg[li]);
    }
    #pragma unroll
    for (int li = 0; li < 8; li++) {
        int idx = t + li * 256;
        wreg[li] = *(const float4*)(Wm + (size_t)(j0 + (idx >> 4)) * KMLP + kbeg + 64 + (idx & 15) * 4);
    }
    #pragma unroll
    for (int li = 0; li < 8; li++) {
        int idx = t + li * 256;
        int row = idx >> 4, seg = idx & 15;
        uint32_t byte = (uint32_t)(row * 128 + ((seg * 8) ^ ((row & 7) << 4)));
        *(uint2*)(sm + K6_STG + K6_W + byte) = cvt4h(wreg[li]);
    }

    int arow_l = lane & 15;
    int acol_l = (lane >> 4) * 16;
    int brow_l = (lane & 7) + ((lane >> 4) << 3);
    int bcol_l = ((lane >> 3) & 1) * 16;

    for (int cch = 0; cch < NCH6; cch++) {
        int s = cch - (cch / 3) * 3;
        uint32_t stg = (uint32_t)(s * K6_STG);
        cpwait1();
        __syncthreads();
        int nxt = cch + 2;
        if (nxt < NCH6) {
            int s2i = nxt - (nxt / 3) * 3;
            uint32_t stg2 = (uint32_t)(s2i * K6_STG);
            int k0n = kbeg + nxt * 64;
            #pragma unroll
            for (int i = 0; i < 2; i++) {
                int idx = t + i * 256;
                int row = idx >> 3, seg = idx & 7;
                uint32_t doff = (uint32_t)(row * 128 + ((seg * 16) ^ ((row & 7) << 4)));
                cpasync16(sb + stg2 + K6_B + doff, g_BM + (size_t)row * KMLP + k0n + seg * 8);
            }
            #pragma unroll
            for (int li = 0; li < 8; li++) {
                int idx = t + li * 256;
                wreg[li] = *(const float4*)(Wm + (size_t)(j0 + (idx >> 4)) * KMLP + k0n + (idx & 15) * 4);
            }
        }
        cpcommit();
        #pragma unroll
        for (int ksp = 0; ksp < 4; ksp++) {
            int kb = ksp * 32;
            uint32_t ah[4][4], bh[4];
            #pragma unroll
            for (int mi = 0; mi < 4; mi++) {
                int row = wj + mi * 16 + arow_l;
                uint32_t off = (uint32_t)(row * 128 + ((kb + acol_l) ^ ((row & 7) << 4)));
                ldsm4(ah[mi], sb + stg + K6_W + off);
            }
            {
                int row = wb + brow_l;
                uint32_t off = (uint32_t)(row * 128 + ((kb + bcol_l) ^ ((row & 7) << 4)));
                ldsm4(bh, sb + stg + K6_B + off);
            }
            #pragma unroll
            for (int mi = 0; mi < 4; mi++)
                #pragma unroll
                for (int j = 0; j < 2; j++)
                    mma16816(c[mi][j], ah[mi], &bh[j * 2]);
        }
        if (nxt < NCH6) {
            int s2i = nxt - (nxt / 3) * 3;
            uint32_t stg2 = (uint32_t)(s2i * K6_STG);
            #pragma unroll
            for (int li = 0; li < 8; li++) {
                int idx = t + li * 256;
                int row = idx >> 4, seg = idx & 15;
                uint32_t byte = (uint32_t)(row * 128 + ((seg * 8) ^ ((row & 7) << 4)));
                *(uint2*)(sm + stg2 + K6_W + byte) = cvt4h(wreg[li]);
            }
        }
    }

    // epilogue: atomicAdd into out[b*MLPD + j]
    #pragma unroll
    for (int mi = 0; mi < 4; mi++) {
        int jr = j0 + wj + mi * 16 + (lane >> 2);
        #pragma unroll
        for (int j = 0; j < 2; j++) {
            int bc = wb + j * 8 + (lane & 3) * 2;
            atomicAdd(outO + (size_t)bc * MLPD + jr,           c[mi][j][0]);
            atomicAdd(outO + (size_t)(bc + 1) * MLPD + jr,     c[mi][j][1]);
            atomicAdd(outO + (size_t)bc * MLPD + jr + 8,       c[mi][j][2]);
            atomicAdd(outO + (size_t)(bc + 1) * MLPD + jr + 8, c[mi][j][3]);
        }
    }
}

// ======================================================================
extern "C" void kernel_launch(void* const* d_in, const int* in_sizes, int n_in,
                              void* d_out, int out_size) {
    const float* enc = nullptr;
    const int*   len = nullptr;
    const float* cat = nullptr;
    const float* W1 = nullptr;
    const float* W2 = nullptr;
    const float* Wm = nullptr;
    const float* bm = nullptr;
    for (int i = 0; i < n_in; i++) {
        switch (in_sizes[i]) {
            case 67108864: enc = (const float*)d_in[i]; break;
            case 64:       len = (const int*)d_in[i];   break;
            case 32768:    cat = (const float*)d_in[i]; break;
            case 537600:   W1  = (const float*)d_in[i]; break;
            case 10500:    W2  = (const float*)d_in[i]; break;
            case 94371840: Wm  = (const float*)d_in[i]; break;
            case 2048:     bm  = (const float*)d_in[i]; break;
            default: break;
        }
    }
    float* outf = (float*)d_out;
    float* outO = outf;
    float* outA = outf + BATCH * MLPD;

    cudaFuncSetAttribute(k1_s1s2, cudaFuncAttributeMaxDynamicSharedMemorySize, K1_SMEM);
    cudaFuncSetAttribute(k6_mlp, cudaFuncAttributeMaxDynamicSharedMemorySize, K6_SMEM);

    kA_prep   <<<4080, 256>>>(W1, W2, cat, bm, outO);
    k1_s1s2   <<<dim3(2, ROWS / 64), 256, K1_SMEM>>>(enc);
    k3_softmax<<<BATCH * RR, 256>>>(len, outA);
    k4_mgemm  <<<dim3(8, BATCH), 256>>>(enc);
    k5b_cat   <<<(BATCH * RR * DCAT) / 1024, 256>>>(cat);
    k6_mlp    <<<dim3(MLPD / 128, KSPLIT), 256, K6_SMEM>>>(Wm, outO);
}